// round 3
// baseline (speedup 1.0000x reference)
#include <cuda_runtime.h>
#include <cstdint>

#define NMAX 100000
#define D 64

__device__ float g_m[(size_t)NMAX * D];
__device__ float g_agg[(size_t)NMAX * D];
__device__ float g_deg[NMAX];

typedef unsigned long long u64;

__device__ __forceinline__ u64 ffma2(u64 a, u64 b, u64 c) {
    u64 d;
    asm("fma.rn.f32x2 %0, %1, %2, %3;" : "=l"(d) : "l"(a), "l"(b), "l"(c));
    return d;
}
__device__ __forceinline__ u64 pack2(float lo, float hi) {
    u64 d; asm("mov.b64 %0, {%1, %2};" : "=l"(d) : "f"(lo), "f"(hi)); return d;
}
__device__ __forceinline__ void unpack2(u64 v, float& lo, float& hi) {
    asm("mov.b64 {%0, %1}, %2;" : "=f"(lo), "=f"(hi) : "l"(v));
}
__device__ __forceinline__ void red_add_v4(float* addr, float4 v) {
    asm volatile("red.global.add.v4.f32 [%0], {%1, %2, %3, %4};"
                 :: "l"(addr), "f"(v.x), "f"(v.y), "f"(v.z), "f"(v.w) : "memory");
}
__device__ __forceinline__ void red_add_f32(float* addr, float v) {
    asm volatile("red.global.add.f32 [%0], %1;" :: "l"(addr), "f"(v) : "memory");
}

// --------------------------------------------------------------------------
__global__ void zero_kernel(int n) {
    int stride = gridDim.x * blockDim.x;
    int tid = blockIdx.x * blockDim.x + threadIdx.x;
    int total4 = n * (D / 4);
    float4 z = make_float4(0.f, 0.f, 0.f, 0.f);
    for (int i = tid; i < total4; i += stride)
        reinterpret_cast<float4*>(g_agg)[i] = z;
    for (int i = tid; i < n; i += stride)
        g_deg[i] = 0.f;
}

// --------------------------------------------------------------------------
// msg: m = relu(x @ W_msg + b)   K=64, node-per-lane, FFMA2.
// smem: Wp[64][32] u64 pairs (W[k][j], W[k][j+32])  = 16 KB
//       bp[32] u64                                   = 256 B
//       xs[8 warps][64][32] float (transposed tile)  = 64 KB
// --------------------------------------------------------------------------
__global__ void __launch_bounds__(256) msg_kernel(
    const float* __restrict__ x, const float* __restrict__ W,
    const float* __restrict__ b, int n)
{
    extern __shared__ char sm[];
    u64*   Wp = (u64*)sm;                       // [64][32]
    u64*   bp = (u64*)(sm + 16384);             // [32]
    float* xs = (float*)(sm + 16384 + 256);     // [8][64][32]

    int tid = threadIdx.x;
    for (int i = tid; i < 64 * 32; i += 256) {
        int k = i >> 5, j = i & 31;
        Wp[i] = pack2(W[k * D + j], W[k * D + j + 32]);
    }
    if (tid < 32) bp[tid] = pack2(b[tid], b[tid + 32]);
    __syncthreads();

    int warp = tid >> 5, lane = tid & 31;
    int group = blockIdx.x * 8 + warp;
    int node = group * 32 + lane;
    bool valid = node < n;
    float* xsw = xs + warp * (64 * 32);

    // stage: transpose this group's x rows into xs[k][lane]
    const float4* xr = reinterpret_cast<const float4*>(x) + (size_t)node * 16;
#pragma unroll
    for (int c = 0; c < 16; c++) {
        float4 v = valid ? xr[c] : make_float4(0.f, 0.f, 0.f, 0.f);
        xsw[(4 * c + 0) * 32 + lane] = v.x;
        xsw[(4 * c + 1) * 32 + lane] = v.y;
        xsw[(4 * c + 2) * 32 + lane] = v.z;
        xsw[(4 * c + 3) * 32 + lane] = v.w;
    }
    __syncwarp();

    u64 acc[32];
    const ulonglong2* bq = (const ulonglong2*)bp;
#pragma unroll
    for (int j2 = 0; j2 < 16; j2++) {
        ulonglong2 t = bq[j2];
        acc[2 * j2] = t.x; acc[2 * j2 + 1] = t.y;
    }

    const float* xcol = xsw + lane;
#pragma unroll 4
    for (int k = 0; k < 64; k++) {
        float xk = xcol[k * 32];
        u64 xx = pack2(xk, xk);
        const ulonglong2* wrow = (const ulonglong2*)(Wp + k * 32);
#pragma unroll
        for (int j2 = 0; j2 < 16; j2++) {
            ulonglong2 wq = wrow[j2];
            acc[2 * j2]     = ffma2(xx, wq.x, acc[2 * j2]);
            acc[2 * j2 + 1] = ffma2(xx, wq.y, acc[2 * j2 + 1]);
        }
    }

    if (valid) {
        float vlo[32], vhi[32];
#pragma unroll
        for (int j = 0; j < 32; j++) {
            float a, c2; unpack2(acc[j], a, c2);
            vlo[j] = fmaxf(a, 0.f); vhi[j] = fmaxf(c2, 0.f);
        }
        float4* mr = reinterpret_cast<float4*>(g_m + (size_t)node * D);
#pragma unroll
        for (int t = 0; t < 8; t++) {
            mr[t]     = make_float4(vlo[4 * t], vlo[4 * t + 1], vlo[4 * t + 2], vlo[4 * t + 3]);
            mr[8 + t] = make_float4(vhi[4 * t], vhi[4 * t + 1], vhi[4 * t + 2], vhi[4 * t + 3]);
        }
    }
}

// --------------------------------------------------------------------------
// edge: agg[dst] += m[src] * w ; deg[dst] += 1   (L2-side red.v4)
// --------------------------------------------------------------------------
__global__ void __launch_bounds__(256) edge_kernel(
    const int* __restrict__ ei, const float* __restrict__ ew, int E)
{
    int t = blockIdx.x * blockDim.x + threadIdx.x;
    int e = t >> 4, sub = t & 15;
    if (e >= E) return;
    int   src = __ldg(ei + e);
    int   dst = __ldg(ei + E + e);
    float w   = __ldg(ew + e);
    const float4 mv = *reinterpret_cast<const float4*>(g_m + (size_t)src * D + sub * 4);
    red_add_v4(g_agg + (size_t)dst * D + sub * 4,
               make_float4(mv.x * w, mv.y * w, mv.z * w, mv.w * w));
    if (sub == 0) red_add_f32(g_deg + dst, 1.0f);
}

// --------------------------------------------------------------------------
// upd: h = relu([x || agg/deg] @ W_upd + b); out = h / max(||h||, 1e-12)
// K=128 in two phases (x half, then agg half) sharing one 8KB/warp tile.
// smem: Wp[128][32] u64 = 32 KB, bp 256 B, xs[8][64][32] = 64 KB
// --------------------------------------------------------------------------
__global__ void __launch_bounds__(256) upd_kernel(
    const float* __restrict__ x, const float* __restrict__ W,
    const float* __restrict__ b, float* __restrict__ out, int n)
{
    extern __shared__ char sm[];
    u64*   Wp = (u64*)sm;                       // [128][32]
    u64*   bp = (u64*)(sm + 32768);             // [32]
    float* xs = (float*)(sm + 32768 + 256);     // [8][64][32]

    int tid = threadIdx.x;
    for (int i = tid; i < 128 * 32; i += 256) {
        int k = i >> 5, j = i & 31;
        Wp[i] = pack2(W[k * D + j], W[k * D + j + 32]);
    }
    if (tid < 32) bp[tid] = pack2(b[tid], b[tid + 32]);
    __syncthreads();

    int warp = tid >> 5, lane = tid & 31;
    int group = blockIdx.x * 8 + warp;
    int node = group * 32 + lane;
    bool valid = node < n;
    float* xsw = xs + warp * (64 * 32);

    float invd = 1.0f;
    if (valid) invd = 1.0f / fmaxf(g_deg[node], 1.0f);

    u64 acc[32];
    const ulonglong2* bq = (const ulonglong2*)bp;
#pragma unroll
    for (int j2 = 0; j2 < 16; j2++) {
        ulonglong2 t = bq[j2];
        acc[2 * j2] = t.x; acc[2 * j2 + 1] = t.y;
    }

    const float* xcol = xsw + lane;

#pragma unroll
    for (int phase = 0; phase < 2; phase++) {
        // stage 64-K half: x for phase 0, agg*invd for phase 1
        const float4* src = (phase == 0)
            ? reinterpret_cast<const float4*>(x) + (size_t)node * 16
            : reinterpret_cast<const float4*>(g_agg) + (size_t)node * 16;
        float s = (phase == 0) ? 1.0f : invd;
#pragma unroll
        for (int c = 0; c < 16; c++) {
            float4 v = valid ? src[c] : make_float4(0.f, 0.f, 0.f, 0.f);
            xsw[(4 * c + 0) * 32 + lane] = v.x * s;
            xsw[(4 * c + 1) * 32 + lane] = v.y * s;
            xsw[(4 * c + 2) * 32 + lane] = v.z * s;
            xsw[(4 * c + 3) * 32 + lane] = v.w * s;
        }
        __syncwarp();

        const u64* Wbase = Wp + (phase * 64) * 32;
#pragma unroll 4
        for (int k = 0; k < 64; k++) {
            float xk = xcol[k * 32];
            u64 xx = pack2(xk, xk);
            const ulonglong2* wrow = (const ulonglong2*)(Wbase + k * 32);
#pragma unroll
            for (int j2 = 0; j2 < 16; j2++) {
                ulonglong2 wq = wrow[j2];
                acc[2 * j2]     = ffma2(xx, wq.x, acc[2 * j2]);
                acc[2 * j2 + 1] = ffma2(xx, wq.y, acc[2 * j2 + 1]);
            }
        }
        __syncwarp();   // protect xs before next phase overwrites (WAR)
    }

    if (valid) {
        float vlo[32], vhi[32];
        float s0 = 0.f, s1 = 0.f, s2 = 0.f, s3 = 0.f;
#pragma unroll
        for (int j = 0; j < 32; j++) {
            float a, c2; unpack2(acc[j], a, c2);
            a = fmaxf(a, 0.f); c2 = fmaxf(c2, 0.f);
            vlo[j] = a; vhi[j] = c2;
            if ((j & 1) == 0) { s0 = fmaf(a, a, s0); s1 = fmaf(c2, c2, s1); }
            else              { s2 = fmaf(a, a, s2); s3 = fmaf(c2, c2, s3); }
        }
        float ss = (s0 + s1) + (s2 + s3);
        float inv = 1.0f / fmaxf(sqrtf(ss), 1e-12f);
        float4* orow = reinterpret_cast<float4*>(out + (size_t)node * D);
#pragma unroll
        for (int t = 0; t < 8; t++) {
            orow[t]     = make_float4(vlo[4 * t] * inv, vlo[4 * t + 1] * inv,
                                      vlo[4 * t + 2] * inv, vlo[4 * t + 3] * inv);
            orow[8 + t] = make_float4(vhi[4 * t] * inv, vhi[4 * t + 1] * inv,
                                      vhi[4 * t + 2] * inv, vhi[4 * t + 3] * inv);
        }
    }
}

// --------------------------------------------------------------------------
extern "C" void kernel_launch(void* const* d_in, const int* in_sizes, int n_in,
                              void* d_out, int out_size)
{
    const float* x  = (const float*)d_in[0];
    const int*   ei = (const int*)  d_in[1];
    const float* ew = (const float*)d_in[2];
    const float* Wm = (const float*)d_in[3];
    const float* bm = (const float*)d_in[4];
    const float* Wu = (const float*)d_in[5];
    const float* bu = (const float*)d_in[6];
    float* out = (float*)d_out;

    int n = in_sizes[0] / D;       // 100000
    int E = in_sizes[1] / 2;       // 1200000
    if (n > NMAX) n = NMAX;

    const int MSG_SMEM = 16384 + 256 + 65536;   // 82176
    const int UPD_SMEM = 32768 + 256 + 65536;   // 98560
    static bool attr_set = false;
    if (!attr_set) {
        cudaFuncSetAttribute(msg_kernel, cudaFuncAttributeMaxDynamicSharedMemorySize, MSG_SMEM);
        cudaFuncSetAttribute(upd_kernel, cudaFuncAttributeMaxDynamicSharedMemorySize, UPD_SMEM);
        attr_set = true;
    }

    int groups = (n + 31) / 32;            // 3125
    int blocks = (groups + 7) / 8;         // 391

    zero_kernel<<<1024, 256>>>(n);
    msg_kernel<<<blocks, 256, MSG_SMEM>>>(x, Wm, bm, n);
    int edge_threads = E * 16;
    edge_kernel<<<(edge_threads + 255) / 256, 256>>>(ei, ew, E);
    upd_kernel<<<blocks, 256, UPD_SMEM>>>(x, Wu, bu, out, n);
}

// round 4
// speedup vs baseline: 1.4060x; 1.4060x over previous
#include <cuda_runtime.h>
#include <cstdint>

#define NMAX 100000
#define D 64
#define NB 8         // nodes per warp-pass (4 pairs)

__device__ float g_m[(size_t)NMAX * D];
__device__ float g_agg[(size_t)NMAX * D];
__device__ float g_deg[NMAX];

typedef unsigned long long u64;

__device__ __forceinline__ u64 ffma2(u64 a, u64 b, u64 c) {
    u64 d;
    asm("fma.rn.f32x2 %0, %1, %2, %3;" : "=l"(d) : "l"(a), "l"(b), "l"(c));
    return d;
}
__device__ __forceinline__ u64 pack2(float lo, float hi) {
    u64 d; asm("mov.b64 %0, {%1, %2};" : "=l"(d) : "f"(lo), "f"(hi)); return d;
}
__device__ __forceinline__ void unpack2(u64 v, float& lo, float& hi) {
    asm("mov.b64 {%0, %1}, %2;" : "=f"(lo), "=f"(hi) : "l"(v));
}
__device__ __forceinline__ void red_add_v4(float* addr, float4 v) {
    asm volatile("red.global.add.v4.f32 [%0], {%1, %2, %3, %4};"
                 :: "l"(addr), "f"(v.x), "f"(v.y), "f"(v.z), "f"(v.w) : "memory");
}
__device__ __forceinline__ void red_add_f32(float* addr, float v) {
    asm volatile("red.global.add.f32 [%0], %1;" :: "l"(addr), "f"(v) : "memory");
}

// --------------------------------------------------------------------------
__global__ void zero_kernel(int n) {
    int stride = gridDim.x * blockDim.x;
    int tid = blockIdx.x * blockDim.x + threadIdx.x;
    int total4 = n * (D / 4);
    float4 z = make_float4(0.f, 0.f, 0.f, 0.f);
    for (int i = tid; i < total4; i += stride)
        reinterpret_cast<float4*>(g_agg)[i] = z;
    for (int i = tid; i < n; i += stride)
        g_deg[i] = 0.f;
}

// --------------------------------------------------------------------------
// msg: m = relu(x @ W_msg + b)   [N,64], K=64
// Warp processes NB=8 nodes (4 pairs). lane = output col j (and j+32).
// acc[nb2] = f32x2 (nodeA, nodeB) for one output col.
// Wq[k2][j] = (W[2k2][j], W[2k2][j+32], W[2k2+1][j], W[2k2+1][j+32])  16 KB
// xp[warp][nb2][k2] = ulonglong2{ pack(xA[2k2],xB[2k2]), pack(xA[2k2+1],xB[2k2+1]) } 16 KB
// --------------------------------------------------------------------------
__global__ void __launch_bounds__(256) msg_kernel(
    const float* __restrict__ x, const float* __restrict__ W,
    const float* __restrict__ b, int n)
{
    __shared__ float4     Wq[D / 2][32];          // 16 KB
    __shared__ ulonglong2 xp[8][NB / 2][D / 2];   // 16 KB

    int tid = threadIdx.x;
    for (int i = tid; i < (D / 2) * 32; i += 256) {
        int k2 = i >> 5, j = i & 31;
        Wq[k2][j] = make_float4(W[(2 * k2) * D + j],     W[(2 * k2) * D + j + 32],
                                W[(2 * k2 + 1) * D + j], W[(2 * k2 + 1) * D + j + 32]);
    }
    __syncthreads();

    int warp = tid >> 5, lane = tid & 31;
    u64 bias0 = pack2(b[lane], b[lane]);
    u64 bias1 = pack2(b[lane + 32], b[lane + 32]);

    int gw = blockIdx.x * 8 + warp;
    int nwp = gridDim.x * 8;

    for (int base = gw * NB; base < n; base += nwp * NB) {
        // ---- stage x pairs (lane covers k2 = lane) ----
#pragma unroll
        for (int p = 0; p < NB / 2; p++) {
            int A = base + 2 * p;
            int B = A + 1;
            int As = min(A, n - 1), Bs = min(B, n - 1);
            float2 ax = reinterpret_cast<const float2*>(x)[(size_t)As * 32 + lane];
            float2 bx = reinterpret_cast<const float2*>(x)[(size_t)Bs * 32 + lane];
            xp[warp][p][lane] = make_ulonglong2(pack2(ax.x, bx.x), pack2(ax.y, bx.y));
        }
        __syncwarp();

        u64 acc0[NB / 2], acc1[NB / 2];
#pragma unroll
        for (int p = 0; p < NB / 2; p++) { acc0[p] = bias0; acc1[p] = bias1; }

#pragma unroll 8
        for (int k2 = 0; k2 < D / 2; k2++) {
            float4 w = Wq[k2][lane];
            u64 w0a = pack2(w.x, w.x);
            u64 w1a = pack2(w.y, w.y);
            u64 w0b = pack2(w.z, w.z);
            u64 w1b = pack2(w.w, w.w);
#pragma unroll
            for (int p = 0; p < NB / 2; p++) {
                ulonglong2 xv = xp[warp][p][k2];     // broadcast
                acc0[p] = ffma2(xv.x, w0a, acc0[p]);
                acc1[p] = ffma2(xv.x, w1a, acc1[p]);
                acc0[p] = ffma2(xv.y, w0b, acc0[p]);
                acc1[p] = ffma2(xv.y, w1b, acc1[p]);
            }
        }

#pragma unroll
        for (int p = 0; p < NB / 2; p++) {
            int A = base + 2 * p, B = A + 1;
            float a0, b0, a1, b1;
            unpack2(acc0[p], a0, b0);
            unpack2(acc1[p], a1, b1);
            if (A < n) {
                float* mr = g_m + (size_t)A * D;
                mr[lane]      = fmaxf(a0, 0.f);
                mr[lane + 32] = fmaxf(a1, 0.f);
            }
            if (B < n) {
                float* mr = g_m + (size_t)B * D;
                mr[lane]      = fmaxf(b0, 0.f);
                mr[lane + 32] = fmaxf(b1, 0.f);
            }
        }
        __syncwarp();
    }
}

// --------------------------------------------------------------------------
// edge: agg[dst] += m[src] * w ; deg[dst] += 1   (L2-side red.v4)
// --------------------------------------------------------------------------
__global__ void __launch_bounds__(256) edge_kernel(
    const int* __restrict__ ei, const float* __restrict__ ew, int E)
{
    int t = blockIdx.x * blockDim.x + threadIdx.x;
    int e = t >> 4, sub = t & 15;
    if (e >= E) return;
    int   src = __ldg(ei + e);
    int   dst = __ldg(ei + E + e);
    float w   = __ldg(ew + e);
    const float4 mv = *reinterpret_cast<const float4*>(g_m + (size_t)src * D + sub * 4);
    red_add_v4(g_agg + (size_t)dst * D + sub * 4,
               make_float4(mv.x * w, mv.y * w, mv.z * w, mv.w * w));
    if (sub == 0) red_add_f32(g_deg + dst, 1.0f);
}

// --------------------------------------------------------------------------
// upd: h = relu([x || agg/deg] @ W_upd + b); out = h / max(||h||,1e-12)
// K=128. Wq 32 KB + xp 32 KB. lane covers k2 = lane (x half) and 32+lane (agg half).
// --------------------------------------------------------------------------
__global__ void __launch_bounds__(256) upd_kernel(
    const float* __restrict__ x, const float* __restrict__ W,
    const float* __restrict__ b, float* __restrict__ out, int n)
{
    __shared__ float4     Wq[D][32];               // 32 KB (2D/2 = 64 k2-rows)
    __shared__ ulonglong2 xp[8][NB / 2][D];        // 32 KB (64 k2 per pair)

    int tid = threadIdx.x;
    for (int i = tid; i < D * 32; i += 256) {
        int k2 = i >> 5, j = i & 31;
        Wq[k2][j] = make_float4(W[(2 * k2) * D + j],     W[(2 * k2) * D + j + 32],
                                W[(2 * k2 + 1) * D + j], W[(2 * k2 + 1) * D + j + 32]);
    }
    __syncthreads();

    int warp = tid >> 5, lane = tid & 31;
    u64 bias0 = pack2(b[lane], b[lane]);
    u64 bias1 = pack2(b[lane + 32], b[lane + 32]);

    int gw = blockIdx.x * 8 + warp;
    int nwp = gridDim.x * 8;

    for (int base = gw * NB; base < n; base += nwp * NB) {
        // ---- stage [x || agg/deg] pairs ----
#pragma unroll
        for (int p = 0; p < NB / 2; p++) {
            int A = base + 2 * p;
            int B = A + 1;
            int As = min(A, n - 1), Bs = min(B, n - 1);
            float2 ax = reinterpret_cast<const float2*>(x)[(size_t)As * 32 + lane];
            float2 bx = reinterpret_cast<const float2*>(x)[(size_t)Bs * 32 + lane];
            xp[warp][p][lane] = make_ulonglong2(pack2(ax.x, bx.x), pack2(ax.y, bx.y));
            float iA = 1.0f / fmaxf(g_deg[As], 1.0f);
            float iB = 1.0f / fmaxf(g_deg[Bs], 1.0f);
            float2 aa = reinterpret_cast<const float2*>(g_agg)[(size_t)As * 32 + lane];
            float2 ba = reinterpret_cast<const float2*>(g_agg)[(size_t)Bs * 32 + lane];
            xp[warp][p][32 + lane] =
                make_ulonglong2(pack2(aa.x * iA, ba.x * iB), pack2(aa.y * iA, ba.y * iB));
        }
        __syncwarp();

        u64 acc0[NB / 2], acc1[NB / 2];
#pragma unroll
        for (int p = 0; p < NB / 2; p++) { acc0[p] = bias0; acc1[p] = bias1; }

#pragma unroll 8
        for (int k2 = 0; k2 < D; k2++) {          // 64 k2-steps (K=128)
            float4 w = Wq[k2][lane];
            u64 w0a = pack2(w.x, w.x);
            u64 w1a = pack2(w.y, w.y);
            u64 w0b = pack2(w.z, w.z);
            u64 w1b = pack2(w.w, w.w);
#pragma unroll
            for (int p = 0; p < NB / 2; p++) {
                ulonglong2 xv = xp[warp][p][k2];   // broadcast
                acc0[p] = ffma2(xv.x, w0a, acc0[p]);
                acc1[p] = ffma2(xv.x, w1a, acc1[p]);
                acc0[p] = ffma2(xv.y, w0b, acc0[p]);
                acc1[p] = ffma2(xv.y, w1b, acc1[p]);
            }
        }

#pragma unroll
        for (int p = 0; p < NB / 2; p++) {
            int A = base + 2 * p, B = A + 1;
            float a0, b0, a1, b1;
            unpack2(acc0[p], a0, b0);
            unpack2(acc1[p], a1, b1);
            a0 = fmaxf(a0, 0.f); a1 = fmaxf(a1, 0.f);
            b0 = fmaxf(b0, 0.f); b1 = fmaxf(b1, 0.f);
            float ssA = fmaf(a0, a0, a1 * a1);
            float ssB = fmaf(b0, b0, b1 * b1);
#pragma unroll
            for (int off = 16; off > 0; off >>= 1) {
                ssA += __shfl_xor_sync(0xFFFFFFFF, ssA, off);
                ssB += __shfl_xor_sync(0xFFFFFFFF, ssB, off);
            }
            float invA = 1.0f / fmaxf(sqrtf(ssA), 1e-12f);
            float invB = 1.0f / fmaxf(sqrtf(ssB), 1e-12f);
            if (A < n) {
                float* orow = out + (size_t)A * D;
                orow[lane]      = a0 * invA;
                orow[lane + 32] = a1 * invA;
            }
            if (B < n) {
                float* orow = out + (size_t)B * D;
                orow[lane]      = b0 * invB;
                orow[lane + 32] = b1 * invB;
            }
        }
        __syncwarp();
    }
}

// --------------------------------------------------------------------------
extern "C" void kernel_launch(void* const* d_in, const int* in_sizes, int n_in,
                              void* d_out, int out_size)
{
    const float* x  = (const float*)d_in[0];
    const int*   ei = (const int*)  d_in[1];
    const float* ew = (const float*)d_in[2];
    const float* Wm = (const float*)d_in[3];
    const float* bm = (const float*)d_in[4];
    const float* Wu = (const float*)d_in[5];
    const float* bu = (const float*)d_in[6];
    float* out = (float*)d_out;

    int n = in_sizes[0] / D;       // 100000
    int E = in_sizes[1] / 2;       // 1200000
    if (n > NMAX) n = NMAX;

    zero_kernel<<<1024, 256>>>(n);
    msg_kernel<<<592, 256>>>(x, Wm, bm, n);
    int edge_threads = E * 16;
    edge_kernel<<<(edge_threads + 255) / 256, 256>>>(ei, ew, E);
    upd_kernel<<<444, 256>>>(x, Wu, bu, out, n);
}